// round 14
// baseline (speedup 1.0000x reference)
#include <cuda_runtime.h>
#include <cuda_bf16.h>
#include <cstdint>
#include <math.h>

#define NB 2
#define CH 512
#define NN1 1024
#define NN2 2048
#define MM1 (NB*NN1)   // 2048 columns
#define MM2 (NB*NN2)   // 4096 columns

typedef __nv_bfloat16 bf16;

// ---------------- device scratch (no allocations allowed) ----------------
__device__ float g_c1[NB*CH];
__device__ float g_cg[NB*CH];
__device__ float g_glob[NB*CH];
__device__ float g_globp[NB*16*CH];
__device__ float g_wx[CH];
__device__ float g_wy[CH];
__device__ int   g_nbr[MM2*64];
__device__ int   g_cnt[MM2];

__device__ __align__(256) bf16 g_aHi[MM2*CH];
__device__ __align__(256) bf16 g_aLo[MM2*CH];
__device__ __align__(256) bf16 g_bHi[MM2*CH];
__device__ __align__(256) bf16 g_bLo[MM2*CH];
__device__ __align__(256) bf16 g_cHi[MM1*CH];   // n1-branch buffers
__device__ __align__(256) bf16 g_cLo[MM1*CH];
__device__ __align__(256) bf16 g_dHi[MM1*CH];
__device__ __align__(256) bf16 g_dLo[MM1*CH];
__device__ __align__(256) bf16 g_featHi[MM2*1024];
__device__ __align__(256) bf16 g_featLo[MM2*1024];

__device__ __align__(256) bf16 g_w1bHi[CH*CH], g_w1bLo[CH*CH];
__device__ __align__(256) bf16 g_w1cHi[CH*CH], g_w1cLo[CH*CH];
__device__ __align__(256) bf16 g_w2aHi[CH*1024], g_w2aLo[CH*1024];
__device__ __align__(256) bf16 g_w2bHi[CH*CH], g_w2bLo[CH*CH];
__device__ __align__(256) bf16 g_w2cHi[CH*CH], g_w2cLo[CH*CH];

#define NEGINF __int_as_float(0xff800000)

// ---------------- host-side streams/events (created at load, before capture) ----
struct HxStreams {
    cudaStream_t s2, s3;
    cudaEvent_t e0, ePrep, eH1n2, eFeat, eCg, eN1;
    HxStreams() {
        cudaStreamCreateWithFlags(&s2, cudaStreamNonBlocking);
        cudaStreamCreateWithFlags(&s3, cudaStreamNonBlocking);
        cudaEventCreateWithFlags(&e0,    cudaEventDisableTiming);
        cudaEventCreateWithFlags(&ePrep, cudaEventDisableTiming);
        cudaEventCreateWithFlags(&eH1n2, cudaEventDisableTiming);
        cudaEventCreateWithFlags(&eFeat, cudaEventDisableTiming);
        cudaEventCreateWithFlags(&eCg,   cudaEventDisableTiming);
        cudaEventCreateWithFlags(&eN1,   cudaEventDisableTiming);
    }
};
static HxStreams g_hx;

// ---------------- PTX helpers (all base-PTX, sm_80-era: safe on compute_103) ----
__device__ __forceinline__ uint32_t smem_u32(const void* p) {
    uint32_t a;
    asm("{ .reg .u64 t; cvta.to.shared.u64 t, %1; cvt.u32.u64 %0, t; }" : "=r"(a) : "l"(p));
    return a;
}
__device__ __forceinline__ void cp16(uint32_t saddr, const void* g) {
    asm volatile("cp.async.cg.shared.global [%0], [%1], 16;" :: "r"(saddr), "l"(g));
}
#define CP_COMMIT() asm volatile("cp.async.commit_group;" ::: "memory")
#define CP_WAIT(n)  asm volatile("cp.async.wait_group %0;" :: "n"(n) : "memory")

__device__ __forceinline__ void ldsm4(uint32_t* r, uint32_t addr) {
    asm volatile("ldmatrix.sync.aligned.m8n8.x4.shared.b16 {%0,%1,%2,%3}, [%4];"
                 : "=r"(r[0]), "=r"(r[1]), "=r"(r[2]), "=r"(r[3]) : "r"(addr));
}
__device__ __forceinline__ void mma16816(float* c, const uint32_t* a, const uint32_t* b) {
    asm volatile("mma.sync.aligned.m16n8k16.row.col.f32.bf16.bf16.f32 "
                 "{%0,%1,%2,%3},{%4,%5,%6,%7},{%8,%9},{%0,%1,%2,%3};"
                 : "+f"(c[0]), "+f"(c[1]), "+f"(c[2]), "+f"(c[3])
                 : "r"(a[0]), "r"(a[1]), "r"(a[2]), "r"(a[3]), "r"(b[0]), "r"(b[1]));
}

__device__ __forceinline__ void split2(float v, bf16& h, bf16& l) {
    h = __float2bfloat16(v);
    l = __float2bfloat16(v - __bfloat162float(h));
}
__device__ __forceinline__ void split_store4(bf16* hi, bf16* lo, float4 v) {
    bf16 h0,l0,h1,l1,h2,l2,h3,l3;
    split2(v.x,h0,l0); split2(v.y,h1,l1); split2(v.z,h2,l2); split2(v.w,h3,l3);
    __nv_bfloat162* hp = (__nv_bfloat162*)hi;
    __nv_bfloat162* lp = (__nv_bfloat162*)lo;
    __nv_bfloat162 a; a.x=h0; a.y=h1; hp[0]=a;
    __nv_bfloat162 b; b.x=h2; b.y=h3; hp[1]=b;
    __nv_bfloat162 c; c.x=l0; c.y=l1; lp[0]=c;
    __nv_bfloat162 d; d.x=l2; d.y=l3; lp[1]=d;
}

// ---------------- fused weight preprocessing (splits only) ----------------
__global__ void k_prep(const float* __restrict__ W1b, const float* __restrict__ W1c,
                       const float* __restrict__ W2b, const float* __restrict__ W2c,
                       const float* __restrict__ W2a) {
    int id = blockIdx.x * 256 + threadIdx.x;
    if (id < 262144) {
        const float* src; bf16 *hi, *lo;
        int seg = id >> 16, off = (id & 65535) * 4;
        if (seg == 0)      { src = W1b; hi = g_w1bHi; lo = g_w1bLo; }
        else if (seg == 1) { src = W1c; hi = g_w1cHi; lo = g_w1cLo; }
        else if (seg == 2) { src = W2b; hi = g_w2bHi; lo = g_w2bLo; }
        else               { src = W2c; hi = g_w2cHi; lo = g_w2cLo; }
        float4 v = *(const float4*)(src + off);
        split_store4(hi + off, lo + off, v);
    } else if (id < 393216) {
        int e = (id - 262144) * 4;
        int r = e >> 10, c = e & 1023;
        float4 v = *(const float4*)(W2a + r * 1536 + c);
        split_store4(g_w2aHi + e, g_w2aLo + e, v);
    }
}

__global__ void k_wxy(const float* __restrict__ W1a) {
    int o = blockIdx.x * 256 + threadIdx.x;
    if (o < CH) { g_wx[o] = W1a[o*514 + 512]; g_wy[o] = W1a[o*514 + 513]; }
}

// ---------------- small kernels ----------------
__global__ void k_dotbias(const float* __restrict__ W, int ldw, int off,
                          const float* __restrict__ vec, const float* __restrict__ bias,
                          float* __restrict__ outv) {
    int w = blockIdx.x * 8 + (threadIdx.x >> 5);
    int lane = threadIdx.x & 31;
    int b = w >> 9, o = w & 511;
    const float* wr = W + o * ldw + off;
    const float* vr = vec + b * CH;
    float acc = 0.f;
    for (int c = lane; c < CH; c += 32) acc = fmaf(wr[c], vr[c], acc);
    #pragma unroll
    for (int s = 16; s; s >>= 1) acc += __shfl_xor_sync(0xffffffffu, acc, s);
    if (lane == 0) outv[w] = acc + bias[o];
}

// templated n/side; 4 channels/thread, float4 coefficient loads.
// grid must be MM/2 blocks of 256.
template <int N_, int SIDE>
__global__ void k_h1(bf16* __restrict__ hi, bf16* __restrict__ lo) {
    int id = blockIdx.x * 256 + threadIdx.x;
    int col = id >> 7, o = (id & 127) * 4;
    int b = (col >= N_) ? 1 : 0;
    int i = col - b * N_;
    int ix = i / SIDE, iy = i - ix * SIDE;
    const float inv = 1.f / (float)(SIDE - 1);
    float lx = (float)ix * inv, ly = (float)iy * inv;
    float4 c4 = *(const float4*)&g_c1[b*CH + o];
    float4 wx = *(const float4*)&g_wx[o];
    float4 wy = *(const float4*)&g_wy[o];
    float4 v;
    v.x = c4.x + wx.x * lx + wy.x * ly;
    v.y = c4.y + wx.y * lx + wy.y * ly;
    v.z = c4.z + wx.z * lx + wy.z * ly;
    v.w = c4.w + wx.w * lx + wy.w * ly;
    v.x = v.x > 0.f ? v.x : 0.2f * v.x;
    v.y = v.y > 0.f ? v.y : 0.2f * v.y;
    v.z = v.z > 0.f ? v.z : 0.2f * v.z;
    v.w = v.w > 0.f ? v.w : 0.2f * v.w;
    split_store4(hi + (size_t)col * CH + o, lo + (size_t)col * CH + o, v);
}

// ---------------- HMMA tensor GEMM: Y = lrelu(bias + X @ W^T) ----------------
// BM=128, BN=64, BK=64. 256 threads (8 warps: 4M x 2N), warp tile 32x32.
// Stage: Ahi 16K | Alo 16K | Bhi 8K | Blo 8K = 48KB; 2 stages = 96KB; 2 blocks/SM.
#define TG_STAGE 49152
#define TG_SMEM  (2*TG_STAGE)

__device__ __forceinline__ uint32_t sw_off(int row, int chunk) {
    return (uint32_t)(row * 128 + ((chunk ^ (row & 7)) * 16));
}

__device__ __forceinline__ void tg_issue(int t, uint32_t s0,
    const bf16* __restrict__ Xhi, const bf16* __restrict__ Xlo, int ldx, int mBase,
    const bf16* __restrict__ Whi, const bf16* __restrict__ Wlo, int ldw, int nBase,
    int k0) {
    #pragma unroll
    for (int j = 0; j < 4; j++) {               // A-hi
        int id = t + 256 * j;
        int r = id >> 3, c = id & 7;
        cp16(s0 + sw_off(r, c), Xhi + (size_t)(mBase + r) * ldx + k0 + c * 8);
    }
    #pragma unroll
    for (int j = 0; j < 4; j++) {               // A-lo
        int id = t + 256 * j;
        int r = id >> 3, c = id & 7;
        cp16(s0 + 16384 + sw_off(r, c), Xlo + (size_t)(mBase + r) * ldx + k0 + c * 8);
    }
    #pragma unroll
    for (int j = 0; j < 2; j++) {               // B-hi
        int id = t + 256 * j;
        int r = id >> 3, c = id & 7;
        cp16(s0 + 32768 + sw_off(r, c), Whi + (size_t)(nBase + r) * ldw + k0 + c * 8);
    }
    #pragma unroll
    for (int j = 0; j < 2; j++) {               // B-lo
        int id = t + 256 * j;
        int r = id >> 3, c = id & 7;
        cp16(s0 + 40960 + sw_off(r, c), Wlo + (size_t)(nBase + r) * ldw + k0 + c * 8);
    }
    CP_COMMIT();
}

__global__ __launch_bounds__(256, 2)
void k_tgemm(const bf16* __restrict__ Xhi, const bf16* __restrict__ Xlo, int ldx,
             const bf16* __restrict__ Whi, const bf16* __restrict__ Wlo, int ldw,
             const float* __restrict__ bias, int biasB,
             bf16* __restrict__ Yhi, bf16* __restrict__ Ylo, int ldy,
             int K, int nPerB) {
    extern __shared__ char sm[];
    uint32_t sbase = smem_u32(sm);
    int t = threadIdx.x, lane = t & 31, w = t >> 5;
    int wm = w & 3, wn = w >> 2;
    int mBase = blockIdx.x * 128, nBase = blockIdx.y * 64;

    float acc[2][4][4];
    #pragma unroll
    for (int mi = 0; mi < 2; mi++)
        #pragma unroll
        for (int nj = 0; nj < 4; nj++)
            #pragma unroll
            for (int q = 0; q < 4; q++) acc[mi][nj][q] = 0.f;

    int rowA0 = wm * 32 + (lane & 15);
    int khA   = lane >> 4;
    int rowB0 = wn * 32 + ((lane >> 4) & 1) * 8 + (lane & 7);
    int khB   = (lane >> 3) & 1;

    int nIter = K >> 6;
    tg_issue(t, sbase, Xhi, Xlo, ldx, mBase, Whi, Wlo, ldw, nBase, 0);

    for (int it = 0; it < nIter; it++) {
        if (it + 1 < nIter) {
            tg_issue(t, sbase + ((it + 1) & 1) * TG_STAGE,
                     Xhi, Xlo, ldx, mBase, Whi, Wlo, ldw, nBase, (it + 1) << 6);
            CP_WAIT(1);
        } else {
            CP_WAIT(0);
        }
        __syncthreads();

        uint32_t sA = sbase + (it & 1) * TG_STAGE;
        uint32_t sB = sA + 32768;
        #pragma unroll
        for (int kt = 0; kt < 4; kt++) {
            uint32_t Af[2][2][4];
            uint32_t Bf[2][2][4];
            #pragma unroll
            for (int mi = 0; mi < 2; mi++) {
                uint32_t off = sw_off(rowA0 + mi * 16, kt * 2 + khA);
                ldsm4(Af[0][mi], sA + off);
                ldsm4(Af[1][mi], sA + 16384 + off);
            }
            #pragma unroll
            for (int pr = 0; pr < 2; pr++) {
                uint32_t off = sw_off(rowB0 + pr * 16, kt * 2 + khB);
                ldsm4(Bf[0][pr], sB + off);
                ldsm4(Bf[1][pr], sB + 8192 + off);
            }
            #pragma unroll
            for (int mi = 0; mi < 2; mi++)
                #pragma unroll
                for (int nj = 0; nj < 4; nj++) {
                    const uint32_t* bh = &Bf[0][nj >> 1][(nj & 1) * 2];
                    const uint32_t* bl = &Bf[1][nj >> 1][(nj & 1) * 2];
                    mma16816(acc[mi][nj], Af[0][mi], bh);
                    mma16816(acc[mi][nj], Af[1][mi], bh);
                    mma16816(acc[mi][nj], Af[0][mi], bl);
                }
        }
        __syncthreads();
    }

    int g = lane >> 2, tq = lane & 3;
    #pragma unroll
    for (int mi = 0; mi < 2; mi++) {
        #pragma unroll
        for (int h = 0; h < 2; h++) {
            int m = mBase + wm * 32 + mi * 16 + g + h * 8;
            const float* bp = bias + ((m >= nPerB) ? biasB : 0);
            size_t ro = (size_t)m * ldy;
            #pragma unroll
            for (int nj = 0; nj < 4; nj++) {
                int n = nBase + wn * 32 + nj * 8 + 2 * tq;
                float v0 = acc[mi][nj][h * 2 + 0] + bp[n];
                float v1 = acc[mi][nj][h * 2 + 1] + bp[n + 1];
                v0 = v0 > 0.f ? v0 : 0.2f * v0;
                v1 = v1 > 0.f ? v1 : 0.2f * v1;
                bf16 h0, l0, h1, l1;
                split2(v0, h0, l0); split2(v1, h1, l1);
                __nv_bfloat162 hh; hh.x = h0; hh.y = h1;
                __nv_bfloat162 ll; ll.x = l0; ll.y = l1;
                *(__nv_bfloat162*)(Yhi + ro + n) = hh;
                *(__nv_bfloat162*)(Ylo + ro + n) = ll;
            }
        }
    }
}

// ---------------- sigmoid heads (bf16x2 loads) ----------------
__global__ void k_head(const bf16* __restrict__ Xhi, const bf16* __restrict__ Xlo, int ldx,
                       const float* __restrict__ Wx, const float* __restrict__ bx,
                       float* __restrict__ outp, const float* __restrict__ fine, int M) {
    int w = blockIdx.x * 8 + (threadIdx.x >> 5);
    int lane = threadIdx.x & 31;
    if (w >= M) return;
    const bf16* hh = Xhi + (size_t)w * ldx;
    const bf16* hl = Xlo + (size_t)w * ldx;
    float a0 = 0.f, a1 = 0.f, a2 = 0.f;
    for (int c = lane * 2; c < CH; c += 64) {
        __nv_bfloat162 h2 = *(const __nv_bfloat162*)(hh + c);
        __nv_bfloat162 l2 = *(const __nv_bfloat162*)(hl + c);
        float va = __bfloat162float(h2.x) + __bfloat162float(l2.x);
        float vb = __bfloat162float(h2.y) + __bfloat162float(l2.y);
        a0 = fmaf(Wx[c], va, fmaf(Wx[c+1], vb, a0));
        a1 = fmaf(Wx[CH + c], va, fmaf(Wx[CH + c + 1], vb, a1));
        a2 = fmaf(Wx[2*CH + c], va, fmaf(Wx[2*CH + c + 1], vb, a2));
    }
    #pragma unroll
    for (int s = 16; s; s >>= 1) {
        a0 += __shfl_xor_sync(0xffffffffu, a0, s);
        a1 += __shfl_xor_sync(0xffffffffu, a1, s);
        a2 += __shfl_xor_sync(0xffffffffu, a2, s);
    }
    if (lane < 3) {
        float a = (lane == 0) ? a0 : ((lane == 1) ? a1 : a2);
        float sv = 1.f / (1.f + expf(-(a + bx[lane]))) - 0.5f;
        if (fine) sv = fine[w*3 + lane] + 0.1f * sv;
        outp[w*3 + lane] = sv;
    }
}

// ---------------- ball query (points cached in smem; stores count) ----------
__global__ void k_ballq(const float* __restrict__ P) {
    __shared__ float sp[NN2 * 3];
    int w = blockIdx.x * 8 + (threadIdx.x >> 5);
    int lane = threadIdx.x & 31;
    int b = w >> 11, i = w & 2047;
    for (int q = threadIdx.x; q < NN2 * 3; q += 256) sp[q] = P[b * NN2 * 3 + q];
    __syncthreads();
    float pix = sp[i*3], piy = sp[i*3+1], piz = sp[i*3+2];
    float sqi = pix*pix + piy*piy + piz*piz;
    int cnt = 0, firstj = 0;
    bool haveFirst = false;
    int base = w * 64;
    for (int jb = 0; jb < NN2; jb += 32) {
        int j = jb + lane;
        float x = sp[j*3], y = sp[j*3+1], zz = sp[j*3+2];
        float d2 = sqi + (x*x + y*y + zz*zz) - 2.f * (pix*x + piy*y + piz*zz);
        bool flag = d2 < 0.01f;
        unsigned mask = __ballot_sync(0xffffffffu, flag);
        int pos = cnt + __popc(mask & ((1u << lane) - 1u));
        if (flag && pos < 64) g_nbr[base + pos] = j;
        if (!haveFirst && mask) { firstj = jb + __ffs(mask) - 1; haveFirst = true; }
        cnt += __popc(mask);
        if (cnt >= 64) break;
    }
    if (cnt < 64)
        for (int tt = cnt + lane; tt < 64; tt += 32) g_nbr[base + tt] = firstj;
    if (lane == 0) g_cnt[w] = min(cnt, 64);
}

// ---------------- global feature max ----------------
__global__ void k_globp() {
    int b = blockIdx.x, chunk = blockIdx.y, o = threadIdx.x;  // 512 threads
    float m = NEGINF;
    size_t base = (size_t)(b * NN2 + chunk * 128) * 1024 + o;
    for (int i = 0; i < 128; i++) {
        float v = __bfloat162float(g_featHi[base + (size_t)i * 1024]) +
                  __bfloat162float(g_featLo[base + (size_t)i * 1024]);
        m = fmaxf(m, v);
    }
    g_globp[(b * 16 + chunk) * CH + o] = m;
}
__global__ void k_globr() {
    int idx = blockIdx.x * 256 + threadIdx.x;
    int b = idx >> 9, o = idx & 511;
    float m = NEGINF;
    for (int c = 0; c < 16; c++) m = fmaxf(m, g_globp[(b * 16 + c) * CH + o]);
    g_glob[idx] = m;
}

// ---------------- neighborhood feature max: hi-only argmax + lo fixup ----------
__global__ void k_local() {
    __shared__ int s[64];
    __shared__ int skc;
    int col = blockIdx.x;
    int b = col >> 11;
    int t = threadIdx.x;  // 128 threads, 4 channels each
    if (t < 64) s[t] = g_nbr[col * 64 + t];
    if (t == 0) skc = g_cnt[col];
    __syncthreads();
    int kcnt = skc;
    int c = t * 4;
    float m0 = NEGINF, m1 = NEGINF, m2 = NEGINF, m3 = NEGINF;
    int a0 = 0, a1 = 0, a2 = 0, a3 = 0;
    #pragma unroll 8
    for (int k = 0; k < kcnt; k++) {
        int j = s[k];
        uint2 hv = *(const uint2*)(g_featHi + (size_t)(b * NN2 + j) * 1024 + c);
        __nv_bfloat162 hA = *(__nv_bfloat162*)&hv.x;
        __nv_bfloat162 hB = *(__nv_bfloat162*)&hv.y;
        float v0 = __bfloat162float(hA.x); if (v0 > m0) { m0 = v0; a0 = j; }
        float v1 = __bfloat162float(hA.y); if (v1 > m1) { m1 = v1; a1 = j; }
        float v2 = __bfloat162float(hB.x); if (v2 > m2) { m2 = v2; a2 = j; }
        float v3 = __bfloat162float(hB.y); if (v3 > m3) { m3 = v3; a3 = j; }
    }
    float r0 = m0 + __bfloat162float(g_featLo[(size_t)(b * NN2 + a0) * 1024 + c]);
    float r1 = m1 + __bfloat162float(g_featLo[(size_t)(b * NN2 + a1) * 1024 + c + 1]);
    float r2 = m2 + __bfloat162float(g_featLo[(size_t)(b * NN2 + a2) * 1024 + c + 2]);
    float r3 = m3 + __bfloat162float(g_featLo[(size_t)(b * NN2 + a3) * 1024 + c + 3]);
    size_t doff = (size_t)col * 1024 + 512 + c;
    bf16 h, l;
    split2(r0, h, l); g_featHi[doff]   = h; g_featLo[doff]   = l;
    split2(r1, h, l); g_featHi[doff+1] = h; g_featLo[doff+1] = l;
    split2(r2, h, l); g_featHi[doff+2] = h; g_featLo[doff+2] = l;
    split2(r3, h, l); g_featHi[doff+3] = h; g_featLo[doff+3] = l;
}

// ---------------- launch ----------------
extern "C" void kernel_launch(void* const* d_in, const int* in_sizes, int n_in,
                              void* d_out, int out_size) {
    const float* z   = (const float*)d_in[0];
    const float* W1a = (const float*)d_in[1];
    const float* b1a = (const float*)d_in[2];
    const float* W1b = (const float*)d_in[3];
    const float* b1b = (const float*)d_in[4];
    const float* W1c = (const float*)d_in[5];
    const float* b1c = (const float*)d_in[6];
    const float* Wx1 = (const float*)d_in[7];
    const float* bx1 = (const float*)d_in[8];
    const float* W2a = (const float*)d_in[9];
    const float* b2a = (const float*)d_in[10];
    const float* W2b = (const float*)d_in[11];
    const float* b2b = (const float*)d_in[12];
    const float* W2c = (const float*)d_in[13];
    const float* b2c = (const float*)d_in[14];
    const float* Wx2 = (const float*)d_in[15];
    const float* bx2 = (const float*)d_in[16];

    float* out  = (float*)d_out;
    float* out1 = out;
    float* out2 = out + MM1 * 3;
    float* outF = out + MM1 * 3 + MM2 * 3;

    float* c1p; cudaGetSymbolAddress((void**)&c1p, g_c1);
    float* cgp; cudaGetSymbolAddress((void**)&cgp, g_cg);
    float* glp; cudaGetSymbolAddress((void**)&glp, g_glob);
    bf16 *aHi, *aLo, *bHi, *bLo, *cHi, *cLo, *dHi, *dLo, *fHi, *fLo;
    cudaGetSymbolAddress((void**)&aHi, g_aHi); cudaGetSymbolAddress((void**)&aLo, g_aLo);
    cudaGetSymbolAddress((void**)&bHi, g_bHi); cudaGetSymbolAddress((void**)&bLo, g_bLo);
    cudaGetSymbolAddress((void**)&cHi, g_cHi); cudaGetSymbolAddress((void**)&cLo, g_cLo);
    cudaGetSymbolAddress((void**)&dHi, g_dHi); cudaGetSymbolAddress((void**)&dLo, g_dLo);
    cudaGetSymbolAddress((void**)&fHi, g_featHi); cudaGetSymbolAddress((void**)&fLo, g_featLo);
    bf16 *w1bH,*w1bL,*w1cH,*w1cL,*w2aH,*w2aL,*w2bH,*w2bL,*w2cH,*w2cL;
    cudaGetSymbolAddress((void**)&w1bH, g_w1bHi); cudaGetSymbolAddress((void**)&w1bL, g_w1bLo);
    cudaGetSymbolAddress((void**)&w1cH, g_w1cHi); cudaGetSymbolAddress((void**)&w1cL, g_w1cLo);
    cudaGetSymbolAddress((void**)&w2aH, g_w2aHi); cudaGetSymbolAddress((void**)&w2aL, g_w2aLo);
    cudaGetSymbolAddress((void**)&w2bH, g_w2bHi); cudaGetSymbolAddress((void**)&w2bL, g_w2bLo);
    cudaGetSymbolAddress((void**)&w2cH, g_w2cHi); cudaGetSymbolAddress((void**)&w2cL, g_w2cLo);

    cudaFuncSetAttribute(k_tgemm, cudaFuncAttributeMaxDynamicSharedMemorySize, TG_SMEM);

    cudaStream_t sd = 0, s2 = g_hx.s2, s3 = g_hx.s3;

    // fork point
    cudaEventRecord(g_hx.e0, sd);
    cudaStreamWaitEvent(s2, g_hx.e0, 0);
    cudaStreamWaitEvent(s3, g_hx.e0, 0);

    // ---- d: weight splits (ordered before d's GEMMs by stream order) ----
    k_prep<<<1536, 256, 0, sd>>>(W1b, W1c, W2b, W2c, W2a);
    cudaEventRecord(g_hx.ePrep, sd);

    // ---- s2: wxy + c1 + both h1's (independent of weight splits) ----
    k_wxy<<<2, 256, 0, s2>>>(W1a);
    k_dotbias<<<128, 256, 0, s2>>>(W1a, 514, 0, z, b1a, c1p);
    k_h1<NN2, 46><<<MM2/2, 256, 0, s2>>>(aHi, aLo);
    cudaEventRecord(g_hx.eH1n2, s2);
    k_h1<NN1, 32><<<MM1/2, 256, 0, s2>>>(cHi, cLo);

    // ---- d: n2 branch runs ALONE (no n1 contention) ----
    cudaStreamWaitEvent(sd, g_hx.eH1n2, 0);
    k_tgemm<<<dim3(MM2/128, 8), 256, TG_SMEM, sd>>>(aHi, aLo, 512, w1bH, w1bL, 512,
                                                    b1b, 0, bHi, bLo, 512, 512, NN2);
    k_tgemm<<<dim3(MM2/128, 8), 256, TG_SMEM, sd>>>(bHi, bLo, 512, w1cH, w1cL, 512,
                                                    b1c, 0, fHi, fLo, 1024, 512, NN2);
    cudaEventRecord(g_hx.eFeat, sd);
    k_head<<<MM2/8, 256, 0, sd>>>(fHi, fLo, 1024, Wx1, bx1, outF, (const float*)0, MM2);

    // ---- s2: n1 branch fills the head/ballq/local window ----
    cudaStreamWaitEvent(s2, g_hx.ePrep, 0);
    cudaStreamWaitEvent(s2, g_hx.eFeat, 0);
    k_tgemm<<<dim3(MM1/128, 8), 256, TG_SMEM, s2>>>(cHi, cLo, 512, w1bH, w1bL, 512,
                                                    b1b, 0, dHi, dLo, 512, 512, NN1);
    k_tgemm<<<dim3(MM1/128, 8), 256, TG_SMEM, s2>>>(dHi, dLo, 512, w1cH, w1cL, 512,
                                                    b1c, 0, cHi, cLo, 512, 512, NN1);
    k_head<<<MM1/8, 256, 0, s2>>>(cHi, cLo, 512, Wx1, bx1, out1, (const float*)0, MM1);
    cudaEventRecord(g_hx.eN1, s2);

    // ---- s3: global-max chain (concurrent with ballq/local on d) ----
    cudaStreamWaitEvent(s3, g_hx.eFeat, 0);
    k_globp<<<dim3(2, 16), 512, 0, s3>>>();
    k_globr<<<4, 256, 0, s3>>>();
    k_dotbias<<<128, 256, 0, s3>>>(W2a, 1536, 1024, glp, b2a, cgp);
    cudaEventRecord(g_hx.eCg, s3);

    // ---- d: ballq + local ----
    k_ballq<<<512, 256, 0, sd>>>(outF);
    k_local<<<MM2, 128, 0, sd>>>();

    // ---- d: join cg + stage2 MLP; join n1 before final head ----
    cudaStreamWaitEvent(sd, g_hx.eCg, 0);
    k_tgemm<<<dim3(MM2/128, 8), 256, TG_SMEM, sd>>>(fHi, fLo, 1024, w2aH, w2aL, 1024,
                                                    cgp, 512, aHi, aLo, 512, 1024, NN2);
    k_tgemm<<<dim3(MM2/128, 8), 256, TG_SMEM, sd>>>(aHi, aLo, 512, w2bH, w2bL, 512,
                                                    b2b, 0, bHi, bLo, 512, 512, NN2);
    k_tgemm<<<dim3(MM2/128, 8), 256, TG_SMEM, sd>>>(bHi, bLo, 512, w2cH, w2cL, 512,
                                                    b2c, 0, aHi, aLo, 512, 512, NN2);
    cudaStreamWaitEvent(sd, g_hx.eN1, 0);
    k_head<<<MM2/8, 256, 0, sd>>>(aHi, aLo, 512, Wx2, bx2, out2, outF, MM2);
}

// round 15
// speedup vs baseline: 1.2393x; 1.2393x over previous
#include <cuda_runtime.h>
#include <cuda_bf16.h>
#include <cuda_fp16.h>
#include <cstdint>
#include <math.h>

#define NB 2
#define CH 512
#define NN1 1024
#define NN2 2048
#define MM1 (NB*NN1)   // 2048 columns
#define MM2 (NB*NN2)   // 4096 columns

typedef __nv_bfloat16 bf16;

// ---------------- device scratch (no allocations allowed) ----------------
__device__ float g_c1[NB*CH];
__device__ float g_cg[NB*CH];
__device__ float g_glob[NB*CH];
__device__ float g_globp[NB*16*CH];
__device__ float g_wx[CH];
__device__ float g_wy[CH];
__device__ int   g_nbr[MM2*64];
__device__ int   g_cnt[MM2];

__device__ __align__(256) bf16 g_aHi[MM2*CH];
__device__ __align__(256) bf16 g_aLo[MM2*CH];
__device__ __align__(256) bf16 g_bHi[MM2*CH];
__device__ __align__(256) bf16 g_bLo[MM2*CH];
__device__ __align__(256) bf16 g_cHi[MM1*CH];   // n1-branch buffers
__device__ __align__(256) bf16 g_cLo[MM1*CH];
__device__ __align__(256) bf16 g_dHi[MM1*CH];
__device__ __align__(256) bf16 g_dLo[MM1*CH];
__device__ __align__(256) bf16 g_featHi[MM2*1024];
__device__ __align__(256) bf16 g_featLo[MM2*1024];

// fp16 shadow for stage-2 (low-precision tier)
__device__ __align__(256) __half g_featF[MM2*1024];
__device__ __align__(256) __half g_h2a[MM2*CH];
__device__ __align__(256) __half g_h2b[MM2*CH];

__device__ __align__(256) bf16 g_w1bHi[CH*CH], g_w1bLo[CH*CH];
__device__ __align__(256) bf16 g_w1cHi[CH*CH], g_w1cLo[CH*CH];
__device__ __align__(256) __half g_w2aF[CH*1024];
__device__ __align__(256) __half g_w2bF[CH*CH];
__device__ __align__(256) __half g_w2cF[CH*CH];

#define NEGINF __int_as_float(0xff800000)

// ---------------- host-side streams/events (created at load, before capture) ----
struct HxStreams {
    cudaStream_t s2, s3;
    cudaEvent_t e0, ePrep, eH1n2, eFeat, eCg, eN1;
    HxStreams() {
        cudaStreamCreateWithFlags(&s2, cudaStreamNonBlocking);
        cudaStreamCreateWithFlags(&s3, cudaStreamNonBlocking);
        cudaEventCreateWithFlags(&e0,    cudaEventDisableTiming);
        cudaEventCreateWithFlags(&ePrep, cudaEventDisableTiming);
        cudaEventCreateWithFlags(&eH1n2, cudaEventDisableTiming);
        cudaEventCreateWithFlags(&eFeat, cudaEventDisableTiming);
        cudaEventCreateWithFlags(&eCg,   cudaEventDisableTiming);
        cudaEventCreateWithFlags(&eN1,   cudaEventDisableTiming);
    }
};
static HxStreams g_hx;

// ---------------- PTX helpers (all base-PTX, sm_80-era: safe on compute_103) ----
__device__ __forceinline__ uint32_t smem_u32(const void* p) {
    uint32_t a;
    asm("{ .reg .u64 t; cvta.to.shared.u64 t, %1; cvt.u32.u64 %0, t; }" : "=r"(a) : "l"(p));
    return a;
}
__device__ __forceinline__ void cp16(uint32_t saddr, const void* g) {
    asm volatile("cp.async.cg.shared.global [%0], [%1], 16;" :: "r"(saddr), "l"(g));
}
#define CP_COMMIT() asm volatile("cp.async.commit_group;" ::: "memory")
#define CP_WAIT(n)  asm volatile("cp.async.wait_group %0;" :: "n"(n) : "memory")

__device__ __forceinline__ void ldsm4(uint32_t* r, uint32_t addr) {
    asm volatile("ldmatrix.sync.aligned.m8n8.x4.shared.b16 {%0,%1,%2,%3}, [%4];"
                 : "=r"(r[0]), "=r"(r[1]), "=r"(r[2]), "=r"(r[3]) : "r"(addr));
}
__device__ __forceinline__ void mma16816(float* c, const uint32_t* a, const uint32_t* b) {
    asm volatile("mma.sync.aligned.m16n8k16.row.col.f32.bf16.bf16.f32 "
                 "{%0,%1,%2,%3},{%4,%5,%6,%7},{%8,%9},{%0,%1,%2,%3};"
                 : "+f"(c[0]), "+f"(c[1]), "+f"(c[2]), "+f"(c[3])
                 : "r"(a[0]), "r"(a[1]), "r"(a[2]), "r"(a[3]), "r"(b[0]), "r"(b[1]));
}
__device__ __forceinline__ void mma16816h(float* c, const uint32_t* a, const uint32_t* b) {
    asm volatile("mma.sync.aligned.m16n8k16.row.col.f32.f16.f16.f32 "
                 "{%0,%1,%2,%3},{%4,%5,%6,%7},{%8,%9},{%0,%1,%2,%3};"
                 : "+f"(c[0]), "+f"(c[1]), "+f"(c[2]), "+f"(c[3])
                 : "r"(a[0]), "r"(a[1]), "r"(a[2]), "r"(a[3]), "r"(b[0]), "r"(b[1]));
}

__device__ __forceinline__ void split2(float v, bf16& h, bf16& l) {
    h = __float2bfloat16(v);
    l = __float2bfloat16(v - __bfloat162float(h));
}
__device__ __forceinline__ void split_store4(bf16* hi, bf16* lo, float4 v) {
    bf16 h0,l0,h1,l1,h2,l2,h3,l3;
    split2(v.x,h0,l0); split2(v.y,h1,l1); split2(v.z,h2,l2); split2(v.w,h3,l3);
    __nv_bfloat162* hp = (__nv_bfloat162*)hi;
    __nv_bfloat162* lp = (__nv_bfloat162*)lo;
    __nv_bfloat162 a; a.x=h0; a.y=h1; hp[0]=a;
    __nv_bfloat162 b; b.x=h2; b.y=h3; hp[1]=b;
    __nv_bfloat162 c; c.x=l0; c.y=l1; lp[0]=c;
    __nv_bfloat162 d; d.x=l2; d.y=l3; lp[1]=d;
}
__device__ __forceinline__ void h_store4(__half* dst, float4 v) {
    __half2* p = (__half2*)dst;
    p[0] = __floats2half2_rn(v.x, v.y);
    p[1] = __floats2half2_rn(v.z, v.w);
}

// ---------------- fused weight preprocessing ----------------
// [0,64K)=W1b bf16split [64K,128K)=W1c bf16split
// [128K,192K)=W2b fp16 [192K,256K)=W2c fp16 [256K,384K)=W2a fp16 (ld1536)
__global__ void k_prep(const float* __restrict__ W1b, const float* __restrict__ W1c,
                       const float* __restrict__ W2b, const float* __restrict__ W2c,
                       const float* __restrict__ W2a) {
    int id = blockIdx.x * 256 + threadIdx.x;
    if (id < 131072) {
        const float* src; bf16 *hi, *lo;
        int seg = id >> 16, off = (id & 65535) * 4;
        if (seg == 0) { src = W1b; hi = g_w1bHi; lo = g_w1bLo; }
        else          { src = W1c; hi = g_w1cHi; lo = g_w1cLo; }
        float4 v = *(const float4*)(src + off);
        split_store4(hi + off, lo + off, v);
    } else if (id < 262144) {
        const float* src; __half* dst;
        int seg = (id - 131072) >> 16, off = ((id - 131072) & 65535) * 4;
        if (seg == 0) { src = W2b; dst = g_w2bF; }
        else          { src = W2c; dst = g_w2cF; }
        float4 v = *(const float4*)(src + off);
        h_store4(dst + off, v);
    } else if (id < 393216) {
        int e = (id - 262144) * 4;
        int r = e >> 10, c = e & 1023;
        float4 v = *(const float4*)(W2a + r * 1536 + c);
        h_store4(g_w2aF + e, v);
    }
}

__global__ void k_wxy(const float* __restrict__ W1a) {
    int o = blockIdx.x * 256 + threadIdx.x;
    if (o < CH) { g_wx[o] = W1a[o*514 + 512]; g_wy[o] = W1a[o*514 + 513]; }
}

// ---------------- small kernels ----------------
__global__ void k_dotbias(const float* __restrict__ W, int ldw, int off,
                          const float* __restrict__ vec, const float* __restrict__ bias,
                          float* __restrict__ outv) {
    int w = blockIdx.x * 8 + (threadIdx.x >> 5);
    int lane = threadIdx.x & 31;
    int b = w >> 9, o = w & 511;
    const float* wr = W + o * ldw + off;
    const float* vr = vec + b * CH;
    float acc = 0.f;
    for (int c = lane; c < CH; c += 32) acc = fmaf(wr[c], vr[c], acc);
    #pragma unroll
    for (int s = 16; s; s >>= 1) acc += __shfl_xor_sync(0xffffffffu, acc, s);
    if (lane == 0) outv[w] = acc + bias[o];
}

template <int N_, int SIDE>
__global__ void k_h1(bf16* __restrict__ hi, bf16* __restrict__ lo) {
    int id = blockIdx.x * 256 + threadIdx.x;
    int col = id >> 7, o = (id & 127) * 4;
    int b = (col >= N_) ? 1 : 0;
    int i = col - b * N_;
    int ix = i / SIDE, iy = i - ix * SIDE;
    const float inv = 1.f / (float)(SIDE - 1);
    float lx = (float)ix * inv, ly = (float)iy * inv;
    float4 c4 = *(const float4*)&g_c1[b*CH + o];
    float4 wx = *(const float4*)&g_wx[o];
    float4 wy = *(const float4*)&g_wy[o];
    float4 v;
    v.x = c4.x + wx.x * lx + wy.x * ly;
    v.y = c4.y + wx.y * lx + wy.y * ly;
    v.z = c4.z + wx.z * lx + wy.z * ly;
    v.w = c4.w + wx.w * lx + wy.w * ly;
    v.x = v.x > 0.f ? v.x : 0.2f * v.x;
    v.y = v.y > 0.f ? v.y : 0.2f * v.y;
    v.z = v.z > 0.f ? v.z : 0.2f * v.z;
    v.w = v.w > 0.f ? v.w : 0.2f * v.w;
    split_store4(hi + (size_t)col * CH + o, lo + (size_t)col * CH + o, v);
}

// ---------------- 3-term compensated bf16 GEMM (stage-1) ----------------
#define TG_STAGE 49152
#define TG_SMEM  (2*TG_STAGE)

__device__ __forceinline__ uint32_t sw_off(int row, int chunk) {
    return (uint32_t)(row * 128 + ((chunk ^ (row & 7)) * 16));
}

__device__ __forceinline__ void tg_issue(int t, uint32_t s0,
    const bf16* __restrict__ Xhi, const bf16* __restrict__ Xlo, int ldx, int mBase,
    const bf16* __restrict__ Whi, const bf16* __restrict__ Wlo, int ldw, int nBase,
    int k0) {
    #pragma unroll
    for (int j = 0; j < 4; j++) {
        int id = t + 256 * j;
        int r = id >> 3, c = id & 7;
        cp16(s0 + sw_off(r, c), Xhi + (size_t)(mBase + r) * ldx + k0 + c * 8);
    }
    #pragma unroll
    for (int j = 0; j < 4; j++) {
        int id = t + 256 * j;
        int r = id >> 3, c = id & 7;
        cp16(s0 + 16384 + sw_off(r, c), Xlo + (size_t)(mBase + r) * ldx + k0 + c * 8);
    }
    #pragma unroll
    for (int j = 0; j < 2; j++) {
        int id = t + 256 * j;
        int r = id >> 3, c = id & 7;
        cp16(s0 + 32768 + sw_off(r, c), Whi + (size_t)(nBase + r) * ldw + k0 + c * 8);
    }
    #pragma unroll
    for (int j = 0; j < 2; j++) {
        int id = t + 256 * j;
        int r = id >> 3, c = id & 7;
        cp16(s0 + 40960 + sw_off(r, c), Wlo + (size_t)(nBase + r) * ldw + k0 + c * 8);
    }
    CP_COMMIT();
}

__global__ __launch_bounds__(256, 2)
void k_tgemm(const bf16* __restrict__ Xhi, const bf16* __restrict__ Xlo, int ldx,
             const bf16* __restrict__ Whi, const bf16* __restrict__ Wlo, int ldw,
             const float* __restrict__ bias, int biasB,
             bf16* __restrict__ Yhi, bf16* __restrict__ Ylo, int ldy,
             int K, int nPerB, __half* __restrict__ Yf) {
    extern __shared__ char sm[];
    uint32_t sbase = smem_u32(sm);
    int t = threadIdx.x, lane = t & 31, w = t >> 5;
    int wm = w & 3, wn = w >> 2;
    int mBase = blockIdx.x * 128, nBase = blockIdx.y * 64;

    float acc[2][4][4];
    #pragma unroll
    for (int mi = 0; mi < 2; mi++)
        #pragma unroll
        for (int nj = 0; nj < 4; nj++)
            #pragma unroll
            for (int q = 0; q < 4; q++) acc[mi][nj][q] = 0.f;

    int rowA0 = wm * 32 + (lane & 15);
    int khA   = lane >> 4;
    int rowB0 = wn * 32 + ((lane >> 4) & 1) * 8 + (lane & 7);
    int khB   = (lane >> 3) & 1;

    int nIter = K >> 6;
    tg_issue(t, sbase, Xhi, Xlo, ldx, mBase, Whi, Wlo, ldw, nBase, 0);

    for (int it = 0; it < nIter; it++) {
        if (it + 1 < nIter) {
            tg_issue(t, sbase + ((it + 1) & 1) * TG_STAGE,
                     Xhi, Xlo, ldx, mBase, Whi, Wlo, ldw, nBase, (it + 1) << 6);
            CP_WAIT(1);
        } else {
            CP_WAIT(0);
        }
        __syncthreads();

        uint32_t sA = sbase + (it & 1) * TG_STAGE;
        uint32_t sB = sA + 32768;
        #pragma unroll
        for (int kt = 0; kt < 4; kt++) {
            uint32_t Af[2][2][4];
            uint32_t Bf[2][2][4];
            #pragma unroll
            for (int mi = 0; mi < 2; mi++) {
                uint32_t off = sw_off(rowA0 + mi * 16, kt * 2 + khA);
                ldsm4(Af[0][mi], sA + off);
                ldsm4(Af[1][mi], sA + 16384 + off);
            }
            #pragma unroll
            for (int pr = 0; pr < 2; pr++) {
                uint32_t off = sw_off(rowB0 + pr * 16, kt * 2 + khB);
                ldsm4(Bf[0][pr], sB + off);
                ldsm4(Bf[1][pr], sB + 8192 + off);
            }
            #pragma unroll
            for (int mi = 0; mi < 2; mi++)
                #pragma unroll
                for (int nj = 0; nj < 4; nj++) {
                    const uint32_t* bh = &Bf[0][nj >> 1][(nj & 1) * 2];
                    const uint32_t* bl = &Bf[1][nj >> 1][(nj & 1) * 2];
                    mma16816(acc[mi][nj], Af[0][mi], bh);
                    mma16816(acc[mi][nj], Af[1][mi], bh);
                    mma16816(acc[mi][nj], Af[0][mi], bl);
                }
        }
        __syncthreads();
    }

    int g = lane >> 2, tq = lane & 3;
    #pragma unroll
    for (int mi = 0; mi < 2; mi++) {
        #pragma unroll
        for (int h = 0; h < 2; h++) {
            int m = mBase + wm * 32 + mi * 16 + g + h * 8;
            const float* bp = bias + ((m >= nPerB) ? biasB : 0);
            size_t ro = (size_t)m * ldy;
            #pragma unroll
            for (int nj = 0; nj < 4; nj++) {
                int n = nBase + wn * 32 + nj * 8 + 2 * tq;
                float v0 = acc[mi][nj][h * 2 + 0] + bp[n];
                float v1 = acc[mi][nj][h * 2 + 1] + bp[n + 1];
                v0 = v0 > 0.f ? v0 : 0.2f * v0;
                v1 = v1 > 0.f ? v1 : 0.2f * v1;
                bf16 h0, l0, h1, l1;
                split2(v0, h0, l0); split2(v1, h1, l1);
                __nv_bfloat162 hh; hh.x = h0; hh.y = h1;
                __nv_bfloat162 ll; ll.x = l0; ll.y = l1;
                *(__nv_bfloat162*)(Yhi + ro + n) = hh;
                *(__nv_bfloat162*)(Ylo + ro + n) = ll;
                if (Yf) *(__half2*)(Yf + ro + n) = __floats2half2_rn(v0, v1);
            }
        }
    }
}

// ---------------- single-term fp16 GEMM (stage-2) ----------------
// Stage: A 16K | B 8K = 24KB; 2 stages = 48KB; 2+ blocks/SM.
#define TH_STAGE 24576
#define TH_SMEM  (2*TH_STAGE)

__device__ __forceinline__ void th_issue(int t, uint32_t s0,
    const __half* __restrict__ Xf, int ldx, int mBase,
    const __half* __restrict__ Wf, int ldw, int nBase, int k0) {
    #pragma unroll
    for (int j = 0; j < 4; j++) {               // A
        int id = t + 256 * j;
        int r = id >> 3, c = id & 7;
        cp16(s0 + sw_off(r, c), Xf + (size_t)(mBase + r) * ldx + k0 + c * 8);
    }
    #pragma unroll
    for (int j = 0; j < 2; j++) {               // B
        int id = t + 256 * j;
        int r = id >> 3, c = id & 7;
        cp16(s0 + 16384 + sw_off(r, c), Wf + (size_t)(nBase + r) * ldw + k0 + c * 8);
    }
    CP_COMMIT();
}

__global__ __launch_bounds__(256, 2)
void k_hgemm(const __half* __restrict__ Xf, int ldx,
             const __half* __restrict__ Wf, int ldw,
             const float* __restrict__ bias, int biasB,
             __half* __restrict__ Yf, int ldy, int K, int nPerB) {
    extern __shared__ char sm[];
    uint32_t sbase = smem_u32(sm);
    int t = threadIdx.x, lane = t & 31, w = t >> 5;
    int wm = w & 3, wn = w >> 2;
    int mBase = blockIdx.x * 128, nBase = blockIdx.y * 64;

    float acc[2][4][4];
    #pragma unroll
    for (int mi = 0; mi < 2; mi++)
        #pragma unroll
        for (int nj = 0; nj < 4; nj++)
            #pragma unroll
            for (int q = 0; q < 4; q++) acc[mi][nj][q] = 0.f;

    int rowA0 = wm * 32 + (lane & 15);
    int khA   = lane >> 4;
    int rowB0 = wn * 32 + ((lane >> 4) & 1) * 8 + (lane & 7);
    int khB   = (lane >> 3) & 1;

    int nIter = K >> 6;
    th_issue(t, sbase, Xf, ldx, mBase, Wf, ldw, nBase, 0);

    for (int it = 0; it < nIter; it++) {
        if (it + 1 < nIter) {
            th_issue(t, sbase + ((it + 1) & 1) * TH_STAGE,
                     Xf, ldx, mBase, Wf, ldw, nBase, (it + 1) << 6);
            CP_WAIT(1);
        } else {
            CP_WAIT(0);
        }
        __syncthreads();

        uint32_t sA = sbase + (it & 1) * TH_STAGE;
        uint32_t sB = sA + 16384;
        #pragma unroll
        for (int kt = 0; kt < 4; kt++) {
            uint32_t Af[2][4];
            uint32_t Bf[2][4];
            #pragma unroll
            for (int mi = 0; mi < 2; mi++)
                ldsm4(Af[mi], sA + sw_off(rowA0 + mi * 16, kt * 2 + khA));
            #pragma unroll
            for (int pr = 0; pr < 2; pr++)
                ldsm4(Bf[pr], sB + sw_off(rowB0 + pr * 16, kt * 2 + khB));
            #pragma unroll
            for (int mi = 0; mi < 2; mi++)
                #pragma unroll
                for (int nj = 0; nj < 4; nj++)
                    mma16816h(acc[mi][nj], Af[mi], &Bf[nj >> 1][(nj & 1) * 2]);
        }
        __syncthreads();
    }

    int g = lane >> 2, tq = lane & 3;
    #pragma unroll
    for (int mi = 0; mi < 2; mi++) {
        #pragma unroll
        for (int h = 0; h < 2; h++) {
            int m = mBase + wm * 32 + mi * 16 + g + h * 8;
            const float* bp = bias + ((m >= nPerB) ? biasB : 0);
            size_t ro = (size_t)m * ldy;
            #pragma unroll
            for (int nj = 0; nj < 4; nj++) {
                int n = nBase + wn * 32 + nj * 8 + 2 * tq;
                float v0 = acc[mi][nj][h * 2 + 0] + bp[n];
                float v1 = acc[mi][nj][h * 2 + 1] + bp[n + 1];
                v0 = v0 > 0.f ? v0 : 0.2f * v0;
                v1 = v1 > 0.f ? v1 : 0.2f * v1;
                *(__half2*)(Yf + ro + n) = __floats2half2_rn(v0, v1);
            }
        }
    }
}

// ---------------- sigmoid heads ----------------
__global__ void k_head(const bf16* __restrict__ Xhi, const bf16* __restrict__ Xlo, int ldx,
                       const float* __restrict__ Wx, const float* __restrict__ bx,
                       float* __restrict__ outp, const float* __restrict__ fine, int M) {
    int w = blockIdx.x * 8 + (threadIdx.x >> 5);
    int lane = threadIdx.x & 31;
    if (w >= M) return;
    const bf16* hh = Xhi + (size_t)w * ldx;
    const bf16* hl = Xlo + (size_t)w * ldx;
    float a0 = 0.f, a1 = 0.f, a2 = 0.f;
    for (int c = lane * 2; c < CH; c += 64) {
        __nv_bfloat162 h2 = *(const __nv_bfloat162*)(hh + c);
        __nv_bfloat162 l2 = *(const __nv_bfloat162*)(hl + c);
        float va = __bfloat162float(h2.x) + __bfloat162float(l2.x);
        float vb = __bfloat162float(h2.y) + __bfloat162float(l2.y);
        a0 = fmaf(Wx[c], va, fmaf(Wx[c+1], vb, a0));
        a1 = fmaf(Wx[CH + c], va, fmaf(Wx[CH + c + 1], vb, a1));
        a2 = fmaf(Wx[2*CH + c], va, fmaf(Wx[2*CH + c + 1], vb, a2));
    }
    #pragma unroll
    for (int s = 16; s; s >>= 1) {
        a0 += __shfl_xor_sync(0xffffffffu, a0, s);
        a1 += __shfl_xor_sync(0xffffffffu, a1, s);
        a2 += __shfl_xor_sync(0xffffffffu, a2, s);
    }
    if (lane < 3) {
        float a = (lane == 0) ? a0 : ((lane == 1) ? a1 : a2);
        float sv = 1.f / (1.f + expf(-(a + bx[lane]))) - 0.5f;
        if (fine) sv = fine[w*3 + lane] + 0.1f * sv;
        outp[w*3 + lane] = sv;
    }
}

__global__ void k_headF(const __half* __restrict__ Xf, int ldx,
                        const float* __restrict__ Wx, const float* __restrict__ bx,
                        float* __restrict__ outp, const float* __restrict__ fine, int M) {
    int w = blockIdx.x * 8 + (threadIdx.x >> 5);
    int lane = threadIdx.x & 31;
    if (w >= M) return;
    const __half* xr = Xf + (size_t)w * ldx;
    float a0 = 0.f, a1 = 0.f, a2 = 0.f;
    for (int c = lane * 2; c < CH; c += 64) {
        __half2 h2 = *(const __half2*)(xr + c);
        float va = __half2float(h2.x), vb = __half2float(h2.y);
        a0 = fmaf(Wx[c], va, fmaf(Wx[c+1], vb, a0));
        a1 = fmaf(Wx[CH + c], va, fmaf(Wx[CH + c + 1], vb, a1));
        a2 = fmaf(Wx[2*CH + c], va, fmaf(Wx[2*CH + c + 1], vb, a2));
    }
    #pragma unroll
    for (int s = 16; s; s >>= 1) {
        a0 += __shfl_xor_sync(0xffffffffu, a0, s);
        a1 += __shfl_xor_sync(0xffffffffu, a1, s);
        a2 += __shfl_xor_sync(0xffffffffu, a2, s);
    }
    if (lane < 3) {
        float a = (lane == 0) ? a0 : ((lane == 1) ? a1 : a2);
        float sv = 1.f / (1.f + expf(-(a + bx[lane]))) - 0.5f;
        if (fine) sv = fine[w*3 + lane] + 0.1f * sv;
        outp[w*3 + lane] = sv;
    }
}

// ---------------- ball query ----------------
__global__ void k_ballq(const float* __restrict__ P) {
    __shared__ float sp[NN2 * 3];
    int w = blockIdx.x * 8 + (threadIdx.x >> 5);
    int lane = threadIdx.x & 31;
    int b = w >> 11, i = w & 2047;
    for (int q = threadIdx.x; q < NN2 * 3; q += 256) sp[q] = P[b * NN2 * 3 + q];
    __syncthreads();
    float pix = sp[i*3], piy = sp[i*3+1], piz = sp[i*3+2];
    float sqi = pix*pix + piy*piy + piz*piz;
    int cnt = 0, firstj = 0;
    bool haveFirst = false;
    int base = w * 64;
    for (int jb = 0; jb < NN2; jb += 32) {
        int j = jb + lane;
        float x = sp[j*3], y = sp[j*3+1], zz = sp[j*3+2];
        float d2 = sqi + (x*x + y*y + zz*zz) - 2.f * (pix*x + piy*y + piz*zz);
        bool flag = d2 < 0.01f;
        unsigned mask = __ballot_sync(0xffffffffu, flag);
        int pos = cnt + __popc(mask & ((1u << lane) - 1u));
        if (flag && pos < 64) g_nbr[base + pos] = j;
        if (!haveFirst && mask) { firstj = jb + __ffs(mask) - 1; haveFirst = true; }
        cnt += __popc(mask);
        if (cnt >= 64) break;
    }
    if (cnt < 64)
        for (int tt = cnt + lane; tt < 64; tt += 32) g_nbr[base + tt] = firstj;
    if (lane == 0) g_cnt[w] = min(cnt, 64);
}

// ---------------- global feature max ----------------
__global__ void k_globp() {
    int b = blockIdx.x, chunk = blockIdx.y, o = threadIdx.x;  // 512 threads
    float m = NEGINF;
    size_t base = (size_t)(b * NN2 + chunk * 128) * 1024 + o;
    for (int i = 0; i < 128; i++) {
        float v = __bfloat162float(g_featHi[base + (size_t)i * 1024]) +
                  __bfloat162float(g_featLo[base + (size_t)i * 1024]);
        m = fmaxf(m, v);
    }
    g_globp[(b * 16 + chunk) * CH + o] = m;
}
__global__ void k_globr() {
    int idx = blockIdx.x * 256 + threadIdx.x;
    int b = idx >> 9, o = idx & 511;
    float m = NEGINF;
    for (int c = 0; c < 16; c++) m = fmaxf(m, g_globp[(b * 16 + c) * CH + o]);
    g_glob[idx] = m;
}

// ---------------- neighborhood max: hi-argmax + lo fixup, fp16 output ---------
__global__ void k_local() {
    __shared__ int s[64];
    __shared__ int skc;
    int col = blockIdx.x;
    int b = col >> 11;
    int t = threadIdx.x;  // 128 threads, 4 channels each
    if (t < 64) s[t] = g_nbr[col * 64 + t];
    if (t == 0) skc = g_cnt[col];
    __syncthreads();
    int kcnt = skc;
    int c = t * 4;
    float m0 = NEGINF, m1 = NEGINF, m2 = NEGINF, m3 = NEGINF;
    int a0 = 0, a1 = 0, a2 = 0, a3 = 0;
    #pragma unroll 8
    for (int k = 0; k < kcnt; k++) {
        int j = s[k];
        uint2 hv = *(const uint2*)(g_featHi + (size_t)(b * NN2 + j) * 1024 + c);
        __nv_bfloat162 hA = *(__nv_bfloat162*)&hv.x;
        __nv_bfloat162 hB = *(__nv_bfloat162*)&hv.y;
        float v0 = __bfloat162float(hA.x); if (v0 > m0) { m0 = v0; a0 = j; }
        float v1 = __bfloat162float(hA.y); if (v1 > m1) { m1 = v1; a1 = j; }
        float v2 = __bfloat162float(hB.x); if (v2 > m2) { m2 = v2; a2 = j; }
        float v3 = __bfloat162float(hB.y); if (v3 > m3) { m3 = v3; a3 = j; }
    }
    float r0 = m0 + __bfloat162float(g_featLo[(size_t)(b * NN2 + a0) * 1024 + c]);
    float r1 = m1 + __bfloat162float(g_featLo[(size_t)(b * NN2 + a1) * 1024 + c + 1]);
    float r2 = m2 + __bfloat162float(g_featLo[(size_t)(b * NN2 + a2) * 1024 + c + 2]);
    float r3 = m3 + __bfloat162float(g_featLo[(size_t)(b * NN2 + a3) * 1024 + c + 3]);
    __half2* dp = (__half2*)(g_featF + (size_t)col * 1024 + 512 + c);
    dp[0] = __floats2half2_rn(r0, r1);
    dp[1] = __floats2half2_rn(r2, r3);
}

// ---------------- launch ----------------
extern "C" void kernel_launch(void* const* d_in, const int* in_sizes, int n_in,
                              void* d_out, int out_size) {
    const float* z   = (const float*)d_in[0];
    const float* W1a = (const float*)d_in[1];
    const float* b1a = (const float*)d_in[2];
    const float* W1b = (const float*)d_in[3];
    const float* b1b = (const float*)d_in[4];
    const float* W1c = (const float*)d_in[5];
    const float* b1c = (const float*)d_in[6];
    const float* Wx1 = (const float*)d_in[7];
    const float* bx1 = (const float*)d_in[8];
    const float* W2a = (const float*)d_in[9];
    const float* b2a = (const float*)d_in[10];
    const float* W2b = (const float*)d_in[11];
    const float* b2b = (const float*)d_in[12];
    const float* W2c = (const float*)d_in[13];
    const float* b2c = (const float*)d_in[14];
    const float* Wx2 = (const float*)d_in[15];
    const float* bx2 = (const float*)d_in[16];

    float* out  = (float*)d_out;
    float* out1 = out;
    float* out2 = out + MM1 * 3;
    float* outF = out + MM1 * 3 + MM2 * 3;

    float* c1p; cudaGetSymbolAddress((void**)&c1p, g_c1);
    float* cgp; cudaGetSymbolAddress((void**)&cgp, g_cg);
    float* glp; cudaGetSymbolAddress((void**)&glp, g_glob);
    bf16 *aHi, *aLo, *bHi, *bLo, *cHi, *cLo, *dHi, *dLo, *fHi, *fLo;
    cudaGetSymbolAddress((void**)&aHi, g_aHi); cudaGetSymbolAddress((void**)&aLo, g_aLo);
    cudaGetSymbolAddress((void**)&bHi, g_bHi); cudaGetSymbolAddress((void**)&bLo, g_bLo);
    cudaGetSymbolAddress((void**)&cHi, g_cHi); cudaGetSymbolAddress((void**)&cLo, g_cLo);
    cudaGetSymbolAddress((void**)&dHi, g_dHi); cudaGetSymbolAddress((void**)&dLo, g_dLo);
    cudaGetSymbolAddress((void**)&fHi, g_featHi); cudaGetSymbolAddress((void**)&fLo, g_featLo);
    __half *fF, *h2a, *h2b, *w2aF, *w2bF, *w2cF;
    cudaGetSymbolAddress((void**)&fF, g_featF);
    cudaGetSymbolAddress((void**)&h2a, g_h2a); cudaGetSymbolAddress((void**)&h2b, g_h2b);
    cudaGetSymbolAddress((void**)&w2aF, g_w2aF);
    cudaGetSymbolAddress((void**)&w2bF, g_w2bF); cudaGetSymbolAddress((void**)&w2cF, g_w2cF);
    bf16 *w1bH,*w1bL,*w1cH,*w1cL;
    cudaGetSymbolAddress((void**)&w1bH, g_w1bHi); cudaGetSymbolAddress((void**)&w1bL, g_w1bLo);
    cudaGetSymbolAddress((void**)&w1cH, g_w1cHi); cudaGetSymbolAddress((void**)&w1cL, g_w1cLo);

    cudaFuncSetAttribute(k_tgemm, cudaFuncAttributeMaxDynamicSharedMemorySize, TG_SMEM);
    cudaFuncSetAttribute(k_hgemm, cudaFuncAttributeMaxDynamicSharedMemorySize, TH_SMEM);

    cudaStream_t sd = 0, s2 = g_hx.s2, s3 = g_hx.s3;
    __half* HNUL = (__half*)0;

    // fork point
    cudaEventRecord(g_hx.e0, sd);
    cudaStreamWaitEvent(s2, g_hx.e0, 0);
    cudaStreamWaitEvent(s3, g_hx.e0, 0);

    // ---- d: weight prep ----
    k_prep<<<1536, 256, 0, sd>>>(W1b, W1c, W2b, W2c, W2a);
    cudaEventRecord(g_hx.ePrep, sd);

    // ---- s2: wxy + c1 + both h1's ----
    k_wxy<<<2, 256, 0, s2>>>(W1a);
    k_dotbias<<<128, 256, 0, s2>>>(W1a, 514, 0, z, b1a, c1p);
    k_h1<NN2, 46><<<MM2/2, 256, 0, s2>>>(aHi, aLo);
    cudaEventRecord(g_hx.eH1n2, s2);
    k_h1<NN1, 32><<<MM1/2, 256, 0, s2>>>(cHi, cLo);

    // ---- d: n2 branch ----
    cudaStreamWaitEvent(sd, g_hx.eH1n2, 0);
    k_tgemm<<<dim3(MM2/128, 8), 256, TG_SMEM, sd>>>(aHi, aLo, 512, w1bH, w1bL, 512,
                                                    b1b, 0, bHi, bLo, 512, 512, NN2, HNUL);
    k_tgemm<<<dim3(MM2/128, 8), 256, TG_SMEM, sd>>>(bHi, bLo, 512, w1cH, w1cL, 512,
                                                    b1c, 0, fHi, fLo, 1024, 512, NN2, fF);
    cudaEventRecord(g_hx.eFeat, sd);
    k_head<<<MM2/8, 256, 0, sd>>>(fHi, fLo, 1024, Wx1, bx1, outF, (const float*)0, MM2);

    // ---- s2: n1 branch fills the head/ballq/local window ----
    cudaStreamWaitEvent(s2, g_hx.ePrep, 0);
    cudaStreamWaitEvent(s2, g_hx.eFeat, 0);
    k_tgemm<<<dim3(MM1/128, 8), 256, TG_SMEM, s2>>>(cHi, cLo, 512, w1bH, w1bL, 512,
                                                    b1b, 0, dHi, dLo, 512, 512, NN1, HNUL);
    k_tgemm<<<dim3(MM1/128, 8), 256, TG_SMEM, s2>>>(dHi, dLo, 512, w1cH, w1cL, 512,
                                                    b1c, 0, cHi, cLo, 512, 512, NN1, HNUL);
    k_head<<<MM1/8, 256, 0, s2>>>(cHi, cLo, 512, Wx1, bx1, out1, (const float*)0, MM1);
    cudaEventRecord(g_hx.eN1, s2);

    // ---- s3: global-max chain ----
    cudaStreamWaitEvent(s3, g_hx.eFeat, 0);
    k_globp<<<dim3(2, 16), 512, 0, s3>>>();
    k_globr<<<4, 256, 0, s3>>>();
    k_dotbias<<<128, 256, 0, s3>>>(W2a, 1536, 1024, glp, b2a, cgp);
    cudaEventRecord(g_hx.eCg, s3);

    // ---- d: ballq + local ----
    k_ballq<<<512, 256, 0, sd>>>(outF);
    k_local<<<MM2, 128, 0, sd>>>();

    // ---- d: stage2 MLP (fp16 single-term) + delta head ----
    cudaStreamWaitEvent(sd, g_hx.eCg, 0);
    k_hgemm<<<dim3(MM2/128, 8), 256, TH_SMEM, sd>>>(fF, 1024, w2aF, 1024,
                                                    cgp, 512, h2a, 512, 1024, NN2);
    k_hgemm<<<dim3(MM2/128, 8), 256, TH_SMEM, sd>>>(h2a, 512, w2bF, 512,
                                                    b2b, 0, h2b, 512, 512, NN2);
    k_hgemm<<<dim3(MM2/128, 8), 256, TH_SMEM, sd>>>(h2b, 512, w2cF, 512,
                                                    b2c, 0, h2a, 512, 512, NN2);
    cudaStreamWaitEvent(sd, g_hx.eN1, 0);
    k_headF<<<MM2/8, 256, 0, sd>>>(h2a, 512, Wx2, bx2, out2, outF, MM2);
}

// round 16
// speedup vs baseline: 1.8233x; 1.4712x over previous
#include <cuda_runtime.h>
#include <cuda_bf16.h>
#include <cuda_fp16.h>
#include <cstdint>
#include <math.h>

#define NB 2
#define CH 512
#define NN1 1024
#define NN2 2048
#define MM1 (NB*NN1)   // 2048 columns
#define MM2 (NB*NN2)   // 4096 columns

// ---------------- device scratch (no allocations allowed) ----------------
__device__ float g_c1[NB*CH];
__device__ float g_cg[NB*CH];
__device__ float g_glob[NB*CH];
__device__ float g_globp[NB*16*CH];
__device__ float g_wx[CH];
__device__ float g_wy[CH];
__device__ int   g_nbr[MM2*64];
__device__ int   g_cnt[MM2];

__device__ __align__(256) __half g_aF[MM2*CH];
__device__ __align__(256) __half g_bF[MM2*CH];
__device__ __align__(256) __half g_cF[MM1*CH];   // n1-branch buffers
__device__ __align__(256) __half g_dF[MM1*CH];
__device__ __align__(256) __half g_featF[MM2*1024];

__device__ __align__(256) __half g_w1bF[CH*CH];
__device__ __align__(256) __half g_w1cF[CH*CH];
__device__ __align__(256) __half g_w2aF[CH*1024];
__device__ __align__(256) __half g_w2bF[CH*CH];
__device__ __align__(256) __half g_w2cF[CH*CH];

#define NEGINF __int_as_float(0xff800000)

// ---------------- host-side streams/events (created at load, before capture) ----
struct HxStreams {
    cudaStream_t s2, s3;
    cudaEvent_t e0, ePrep, eH1n2, eFeat, eCg, eN1;
    HxStreams() {
        cudaStreamCreateWithFlags(&s2, cudaStreamNonBlocking);
        cudaStreamCreateWithFlags(&s3, cudaStreamNonBlocking);
        cudaEventCreateWithFlags(&e0,    cudaEventDisableTiming);
        cudaEventCreateWithFlags(&ePrep, cudaEventDisableTiming);
        cudaEventCreateWithFlags(&eH1n2, cudaEventDisableTiming);
        cudaEventCreateWithFlags(&eFeat, cudaEventDisableTiming);
        cudaEventCreateWithFlags(&eCg,   cudaEventDisableTiming);
        cudaEventCreateWithFlags(&eN1,   cudaEventDisableTiming);
    }
};
static HxStreams g_hx;

// ---------------- PTX helpers (all base-PTX, sm_80-era: safe on compute_103) ----
__device__ __forceinline__ uint32_t smem_u32(const void* p) {
    uint32_t a;
    asm("{ .reg .u64 t; cvta.to.shared.u64 t, %1; cvt.u32.u64 %0, t; }" : "=r"(a) : "l"(p));
    return a;
}
__device__ __forceinline__ void cp16(uint32_t saddr, const void* g) {
    asm volatile("cp.async.cg.shared.global [%0], [%1], 16;" :: "r"(saddr), "l"(g));
}
#define CP_COMMIT() asm volatile("cp.async.commit_group;" ::: "memory")
#define CP_WAIT(n)  asm volatile("cp.async.wait_group %0;" :: "n"(n) : "memory")

__device__ __forceinline__ void ldsm4(uint32_t* r, uint32_t addr) {
    asm volatile("ldmatrix.sync.aligned.m8n8.x4.shared.b16 {%0,%1,%2,%3}, [%4];"
                 : "=r"(r[0]), "=r"(r[1]), "=r"(r[2]), "=r"(r[3]) : "r"(addr));
}
__device__ __forceinline__ void mma16816h(float* c, const uint32_t* a, const uint32_t* b) {
    asm volatile("mma.sync.aligned.m16n8k16.row.col.f32.f16.f16.f32 "
                 "{%0,%1,%2,%3},{%4,%5,%6,%7},{%8,%9},{%0,%1,%2,%3};"
                 : "+f"(c[0]), "+f"(c[1]), "+f"(c[2]), "+f"(c[3])
                 : "r"(a[0]), "r"(a[1]), "r"(a[2]), "r"(a[3]), "r"(b[0]), "r"(b[1]));
}

__device__ __forceinline__ void h_store4(__half* dst, float4 v) {
    __half2* p = (__half2*)dst;
    p[0] = __floats2half2_rn(v.x, v.y);
    p[1] = __floats2half2_rn(v.z, v.w);
}

// ---------------- fused weight preprocessing (all fp16) ----------------
// id segments (float4 units): [0,64K)=W1b [64K,128K)=W1c [128K,192K)=W2b
// [192K,256K)=W2c  [256K,384K)=W2a (ld1536, 1024 cols)
__global__ void k_prep(const float* __restrict__ W1b, const float* __restrict__ W1c,
                       const float* __restrict__ W2b, const float* __restrict__ W2c,
                       const float* __restrict__ W2a) {
    int id = blockIdx.x * 256 + threadIdx.x;
    if (id < 262144) {
        const float* src; __half* dst;
        int seg = id >> 16, off = (id & 65535) * 4;
        if (seg == 0)      { src = W1b; dst = g_w1bF; }
        else if (seg == 1) { src = W1c; dst = g_w1cF; }
        else if (seg == 2) { src = W2b; dst = g_w2bF; }
        else               { src = W2c; dst = g_w2cF; }
        float4 v = *(const float4*)(src + off);
        h_store4(dst + off, v);
    } else if (id < 393216) {
        int e = (id - 262144) * 4;
        int r = e >> 10, c = e & 1023;
        float4 v = *(const float4*)(W2a + r * 1536 + c);
        h_store4(g_w2aF + e, v);
    }
}

__global__ void k_wxy(const float* __restrict__ W1a) {
    int o = blockIdx.x * 256 + threadIdx.x;
    if (o < CH) { g_wx[o] = W1a[o*514 + 512]; g_wy[o] = W1a[o*514 + 513]; }
}

// ---------------- small kernels ----------------
__global__ void k_dotbias(const float* __restrict__ W, int ldw, int off,
                          const float* __restrict__ vec, const float* __restrict__ bias,
                          float* __restrict__ outv) {
    int w = blockIdx.x * 8 + (threadIdx.x >> 5);
    int lane = threadIdx.x & 31;
    int b = w >> 9, o = w & 511;
    const float* wr = W + o * ldw + off;
    const float* vr = vec + b * CH;
    float acc = 0.f;
    for (int c = lane; c < CH; c += 32) acc = fmaf(wr[c], vr[c], acc);
    #pragma unroll
    for (int s = 16; s; s >>= 1) acc += __shfl_xor_sync(0xffffffffu, acc, s);
    if (lane == 0) outv[w] = acc + bias[o];
}

// templated n/side; 4 channels/thread; fp16 output. grid = MM/2 blocks of 256.
template <int N_, int SIDE>
__global__ void k_h1(__half* __restrict__ dst) {
    int id = blockIdx.x * 256 + threadIdx.x;
    int col = id >> 7, o = (id & 127) * 4;
    int b = (col >= N_) ? 1 : 0;
    int i = col - b * N_;
    int ix = i / SIDE, iy = i - ix * SIDE;
    const float inv = 1.f / (float)(SIDE - 1);
    float lx = (float)ix * inv, ly = (float)iy * inv;
    float4 c4 = *(const float4*)&g_c1[b*CH + o];
    float4 wx = *(const float4*)&g_wx[o];
    float4 wy = *(const float4*)&g_wy[o];
    float4 v;
    v.x = c4.x + wx.x * lx + wy.x * ly;
    v.y = c4.y + wx.y * lx + wy.y * ly;
    v.z = c4.z + wx.z * lx + wy.z * ly;
    v.w = c4.w + wx.w * lx + wy.w * ly;
    v.x = v.x > 0.f ? v.x : 0.2f * v.x;
    v.y = v.y > 0.f ? v.y : 0.2f * v.y;
    v.z = v.z > 0.f ? v.z : 0.2f * v.z;
    v.w = v.w > 0.f ? v.w : 0.2f * v.w;
    h_store4(dst + (size_t)col * CH + o, v);
}

// ---------------- fp16 HMMA GEMM: Y = lrelu(bias + X @ W^T) ----------------
// BM=128, BN=64, BK=64. 256 threads (8 warps: 4M x 2N), warp tile 32x32.
// Stage: A 16K | B 8K = 24KB; 2 stages = 48KB.
#define TH_STAGE 24576
#define TH_SMEM  (2*TH_STAGE)

__device__ __forceinline__ uint32_t sw_off(int row, int chunk) {
    return (uint32_t)(row * 128 + ((chunk ^ (row & 7)) * 16));
}

__device__ __forceinline__ void th_issue(int t, uint32_t s0,
    const __half* __restrict__ Xf, int ldx, int mBase,
    const __half* __restrict__ Wf, int ldw, int nBase, int k0) {
    #pragma unroll
    for (int j = 0; j < 4; j++) {               // A
        int id = t + 256 * j;
        int r = id >> 3, c = id & 7;
        cp16(s0 + sw_off(r, c), Xf + (size_t)(mBase + r) * ldx + k0 + c * 8);
    }
    #pragma unroll
    for (int j = 0; j < 2; j++) {               // B
        int id = t + 256 * j;
        int r = id >> 3, c = id & 7;
        cp16(s0 + 16384 + sw_off(r, c), Wf + (size_t)(nBase + r) * ldw + k0 + c * 8);
    }
    CP_COMMIT();
}

__global__ __launch_bounds__(256, 2)
void k_hgemm(const __half* __restrict__ Xf, int ldx,
             const __half* __restrict__ Wf, int ldw,
             const float* __restrict__ bias, int biasB,
             __half* __restrict__ Yf, int ldy, int K, int nPerB) {
    extern __shared__ char sm[];
    uint32_t sbase = smem_u32(sm);
    int t = threadIdx.x, lane = t & 31, w = t >> 5;
    int wm = w & 3, wn = w >> 2;
    int mBase = blockIdx.x * 128, nBase = blockIdx.y * 64;

    float acc[2][4][4];
    #pragma unroll
    for (int mi = 0; mi < 2; mi++)
        #pragma unroll
        for (int nj = 0; nj < 4; nj++)
            #pragma unroll
            for (int q = 0; q < 4; q++) acc[mi][nj][q] = 0.f;

    int rowA0 = wm * 32 + (lane & 15);
    int khA   = lane >> 4;
    int rowB0 = wn * 32 + ((lane >> 4) & 1) * 8 + (lane & 7);
    int khB   = (lane >> 3) & 1;

    int nIter = K >> 6;
    th_issue(t, sbase, Xf, ldx, mBase, Wf, ldw, nBase, 0);

    for (int it = 0; it < nIter; it++) {
        if (it + 1 < nIter) {
            th_issue(t, sbase + ((it + 1) & 1) * TH_STAGE,
                     Xf, ldx, mBase, Wf, ldw, nBase, (it + 1) << 6);
            CP_WAIT(1);
        } else {
            CP_WAIT(0);
        }
        __syncthreads();

        uint32_t sA = sbase + (it & 1) * TH_STAGE;
        uint32_t sB = sA + 16384;
        #pragma unroll
        for (int kt = 0; kt < 4; kt++) {
            uint32_t Af[2][4];
            uint32_t Bf[2][4];
            #pragma unroll
            for (int mi = 0; mi < 2; mi++)
                ldsm4(Af[mi], sA + sw_off(rowA0 + mi * 16, kt * 2 + khA));
            #pragma unroll
            for (int pr = 0; pr < 2; pr++)
                ldsm4(Bf[pr], sB + sw_off(rowB0 + pr * 16, kt * 2 + khB));
            #pragma unroll
            for (int mi = 0; mi < 2; mi++)
                #pragma unroll
                for (int nj = 0; nj < 4; nj++)
                    mma16816h(acc[mi][nj], Af[mi], &Bf[nj >> 1][(nj & 1) * 2]);
        }
        __syncthreads();
    }

    int g = lane >> 2, tq = lane & 3;
    #pragma unroll
    for (int mi = 0; mi < 2; mi++) {
        #pragma unroll
        for (int h = 0; h < 2; h++) {
            int m = mBase + wm * 32 + mi * 16 + g + h * 8;
            const float* bp = bias + ((m >= nPerB) ? biasB : 0);
            size_t ro = (size_t)m * ldy;
            #pragma unroll
            for (int nj = 0; nj < 4; nj++) {
                int n = nBase + wn * 32 + nj * 8 + 2 * tq;
                float v0 = acc[mi][nj][h * 2 + 0] + bp[n];
                float v1 = acc[mi][nj][h * 2 + 1] + bp[n + 1];
                v0 = v0 > 0.f ? v0 : 0.2f * v0;
                v1 = v1 > 0.f ? v1 : 0.2f * v1;
                *(__half2*)(Yf + ro + n) = __floats2half2_rn(v0, v1);
            }
        }
    }
}

// ---------------- sigmoid head (fp16 input) ----------------
__global__ void k_headF(const __half* __restrict__ Xf, int ldx,
                        const float* __restrict__ Wx, const float* __restrict__ bx,
                        float* __restrict__ outp, const float* __restrict__ fine, int M) {
    int w = blockIdx.x * 8 + (threadIdx.x >> 5);
    int lane = threadIdx.x & 31;
    if (w >= M) return;
    const __half* xr = Xf + (size_t)w * ldx;
    float a0 = 0.f, a1 = 0.f, a2 = 0.f;
    for (int c = lane * 2; c < CH; c += 64) {
        __half2 h2 = *(const __half2*)(xr + c);
        float va = __half2float(h2.x), vb = __half2float(h2.y);
        a0 = fmaf(Wx[c], va, fmaf(Wx[c+1], vb, a0));
        a1 = fmaf(Wx[CH + c], va, fmaf(Wx[CH + c + 1], vb, a1));
        a2 = fmaf(Wx[2*CH + c], va, fmaf(Wx[2*CH + c + 1], vb, a2));
    }
    #pragma unroll
    for (int s = 16; s; s >>= 1) {
        a0 += __shfl_xor_sync(0xffffffffu, a0, s);
        a1 += __shfl_xor_sync(0xffffffffu, a1, s);
        a2 += __shfl_xor_sync(0xffffffffu, a2, s);
    }
    if (lane < 3) {
        float a = (lane == 0) ? a0 : ((lane == 1) ? a1 : a2);
        float sv = 1.f / (1.f + expf(-(a + bx[lane]))) - 0.5f;
        if (fine) sv = fine[w*3 + lane] + 0.1f * sv;
        outp[w*3 + lane] = sv;
    }
}

// ---------------- ball query ----------------
__global__ void k_ballq(const float* __restrict__ P) {
    __shared__ float sp[NN2 * 3];
    int w = blockIdx.x * 8 + (threadIdx.x >> 5);
    int lane = threadIdx.x & 31;
    int b = w >> 11, i = w & 2047;
    for (int q = threadIdx.x; q < NN2 * 3; q += 256) sp[q] = P[b * NN2 * 3 + q];
    __syncthreads();
    float pix = sp[i*3], piy = sp[i*3+1], piz = sp[i*3+2];
    float sqi = pix*pix + piy*piy + piz*piz;
    int cnt = 0, firstj = 0;
    bool haveFirst = false;
    int base = w * 64;
    for (int jb = 0; jb < NN2; jb += 32) {
        int j = jb + lane;
        float x = sp[j*3], y = sp[j*3+1], zz = sp[j*3+2];
        float d2 = sqi + (x*x + y*y + zz*zz) - 2.f * (pix*x + piy*y + piz*zz);
        bool flag = d2 < 0.01f;
        unsigned mask = __ballot_sync(0xffffffffu, flag);
        int pos = cnt + __popc(mask & ((1u << lane) - 1u));
        if (flag && pos < 64) g_nbr[base + pos] = j;
        if (!haveFirst && mask) { firstj = jb + __ffs(mask) - 1; haveFirst = true; }
        cnt += __popc(mask);
        if (cnt >= 64) break;
    }
    if (cnt < 64)
        for (int tt = cnt + lane; tt < 64; tt += 32) g_nbr[base + tt] = firstj;
    if (lane == 0) g_cnt[w] = min(cnt, 64);
}

// ---------------- global feature max (fp16 feats) ----------------
__global__ void k_globp() {
    int b = blockIdx.x, chunk = blockIdx.y, o = threadIdx.x;  // 512 threads
    float m = NEGINF;
    size_t base = (size_t)(b * NN2 + chunk * 128) * 1024 + o;
    for (int i = 0; i < 128; i++)
        m = fmaxf(m, __half2float(g_featF[base + (size_t)i * 1024]));
    g_globp[(b * 16 + chunk) * CH + o] = m;
}
__global__ void k_globr() {
    int idx = blockIdx.x * 256 + threadIdx.x;
    int b = idx >> 9, o = idx & 511;
    float m = NEGINF;
    for (int c = 0; c < 16; c++) m = fmaxf(m, g_globp[(b * 16 + c) * CH + o]);
    g_glob[idx] = m;
}

// ---------------- neighborhood feature max (exact, fp16) ----------------
__global__ void k_local() {
    __shared__ int s[64];
    __shared__ int skc;
    int col = blockIdx.x;
    int b = col >> 11;
    int t = threadIdx.x;  // 128 threads, 4 channels each
    if (t < 64) s[t] = g_nbr[col * 64 + t];
    if (t == 0) skc = g_cnt[col];
    __syncthreads();
    int kcnt = skc;
    int c = t * 4;
    float m0 = NEGINF, m1 = NEGINF, m2 = NEGINF, m3 = NEGINF;
    #pragma unroll 8
    for (int k = 0; k < kcnt; k++) {
        int j = s[k];
        uint2 hv = *(const uint2*)(g_featF + (size_t)(b * NN2 + j) * 1024 + c);
        __half2 hA = *(__half2*)&hv.x;
        __half2 hB = *(__half2*)&hv.y;
        m0 = fmaxf(m0, __half2float(hA.x));
        m1 = fmaxf(m1, __half2float(hA.y));
        m2 = fmaxf(m2, __half2float(hB.x));
        m3 = fmaxf(m3, __half2float(hB.y));
    }
    __half2* dp = (__half2*)(g_featF + (size_t)col * 1024 + 512 + c);
    dp[0] = __floats2half2_rn(m0, m1);
    dp[1] = __floats2half2_rn(m2, m3);
}

// ---------------- launch ----------------
extern "C" void kernel_launch(void* const* d_in, const int* in_sizes, int n_in,
                              void* d_out, int out_size) {
    const float* z   = (const float*)d_in[0];
    const float* W1a = (const float*)d_in[1];
    const float* b1a = (const float*)d_in[2];
    const float* W1b = (const float*)d_in[3];
    const float* b1b = (const float*)d_in[4];
    const float* W1c = (const float*)d_in[5];
    const float* b1c = (const float*)d_in[6];
    const float* Wx1 = (const float*)d_in[7];
    const float* bx1 = (const float*)d_in[8];
    const float* W2a = (const float*)d_in[9];
    const float* b2a = (const float*)d_in[10];
    const float* W2b = (const float*)d_in[11];
    const float* b2b = (const float*)d_in[12];
    const float* W2c = (const float*)d_in[13];
    const float* b2c = (const float*)d_in[14];
    const float* Wx2 = (const float*)d_in[15];
    const float* bx2 = (const float*)d_in[16];

    float* out  = (float*)d_out;
    float* out1 = out;
    float* out2 = out + MM1 * 3;
    float* outF = out + MM1 * 3 + MM2 * 3;

    float* c1p; cudaGetSymbolAddress((void**)&c1p, g_c1);
    float* cgp; cudaGetSymbolAddress((void**)&cgp, g_cg);
    float* glp; cudaGetSymbolAddress((void**)&glp, g_glob);
    __half *aF, *bF, *cF, *dF, *fF;
    cudaGetSymbolAddress((void**)&aF, g_aF); cudaGetSymbolAddress((void**)&bF, g_bF);
    cudaGetSymbolAddress((void**)&cF, g_cF); cudaGetSymbolAddress((void**)&dF, g_dF);
    cudaGetSymbolAddress((void**)&fF, g_featF);
    __half *w1bF, *w1cF, *w2aF, *w2bF, *w2cF;
    cudaGetSymbolAddress((void**)&w1bF, g_w1bF); cudaGetSymbolAddress((void**)&w1cF, g_w1cF);
    cudaGetSymbolAddress((void**)&w2aF, g_w2aF);
    cudaGetSymbolAddress((void**)&w2bF, g_w2bF); cudaGetSymbolAddress((void**)&w2cF, g_w2cF);

    cudaFuncSetAttribute(k_hgemm, cudaFuncAttributeMaxDynamicSharedMemorySize, TH_SMEM);

    cudaStream_t sd = 0, s2 = g_hx.s2, s3 = g_hx.s3;

    // fork point
    cudaEventRecord(g_hx.e0, sd);
    cudaStreamWaitEvent(s2, g_hx.e0, 0);
    cudaStreamWaitEvent(s3, g_hx.e0, 0);

    // ---- d: weight prep (all fp16 conversions) ----
    k_prep<<<1536, 256, 0, sd>>>(W1b, W1c, W2b, W2c, W2a);
    cudaEventRecord(g_hx.ePrep, sd);

    // ---- s2: wxy + c1 + both h1's ----
    k_wxy<<<2, 256, 0, s2>>>(W1a);
    k_dotbias<<<128, 256, 0, s2>>>(W1a, 514, 0, z, b1a, c1p);
    k_h1<NN2, 46><<<MM2/2, 256, 0, s2>>>(aF);
    cudaEventRecord(g_hx.eH1n2, s2);
    k_h1<NN1, 32><<<MM1/2, 256, 0, s2>>>(cF);

    // ---- d: n2 branch (prep ordered before by stream order) ----
    cudaStreamWaitEvent(sd, g_hx.eH1n2, 0);
    k_hgemm<<<dim3(MM2/128, 8), 256, TH_SMEM, sd>>>(aF, 512, w1bF, 512,
                                                    b1b, 0, bF, 512, 512, NN2);
    k_hgemm<<<dim3(MM2/128, 8), 256, TH_SMEM, sd>>>(bF, 512, w1cF, 512,
                                                    b1c, 0, fF, 1024, 512, NN2);
    cudaEventRecord(g_hx.eFeat, sd);
    k_headF<<<MM2/8, 256, 0, sd>>>(fF, 1024, Wx1, bx1, outF, (const float*)0, MM2);

    // ---- s2: n1 branch fills the head/ballq/local window ----
    cudaStreamWaitEvent(s2, g_hx.ePrep, 0);
    cudaStreamWaitEvent(s2, g_hx.eFeat, 0);
    k_hgemm<<<dim3(MM1/128, 8), 256, TH_SMEM, s2>>>(cF, 512, w1bF, 512,
                                                    b1b, 0, dF, 512, 512, NN1);
    k_hgemm<<<dim3(MM1/128, 8), 256, TH_SMEM, s2>>>(dF, 512, w1cF, 512,
                                                    b1c, 0, cF, 512, 512, NN1);
    k_headF<<<MM1/8, 256, 0, s2>>>(cF, 512, Wx1, bx1, out1, (const float*)0, MM1);
    cudaEventRecord(g_hx.eN1, s2);

    // ---- s3: global-max chain ----
    cudaStreamWaitEvent(s3, g_hx.eFeat, 0);
    k_globp<<<dim3(2, 16), 512, 0, s3>>>();
    k_globr<<<4, 256, 0, s3>>>();
    k_dotbias<<<128, 256, 0, s3>>>(W2a, 1536, 1024, glp, b2a, cgp);
    cudaEventRecord(g_hx.eCg, s3);

    // ---- d: ballq + local ----
    k_ballq<<<512, 256, 0, sd>>>(outF);
    k_local<<<MM2, 128, 0, sd>>>();

    // ---- d: stage2 MLP (fp16) + delta head ----
    cudaStreamWaitEvent(sd, g_hx.eCg, 0);
    k_hgemm<<<dim3(MM2/128, 8), 256, TH_SMEM, sd>>>(fF, 1024, w2aF, 1024,
                                                    cgp, 512, aF, 512, 1024, NN2);
    k_hgemm<<<dim3(MM2/128, 8), 256, TH_SMEM, sd>>>(aF, 512, w2bF, 512,
                                                    b2b, 0, bF, 512, 512, NN2);
    k_hgemm<<<dim3(MM2/128, 8), 256, TH_SMEM, sd>>>(bF, 512, w2cF, 512,
                                                    b2c, 0, aF, 512, 512, NN2);
    cudaStreamWaitEvent(sd, g_hx.eN1, 0);
    k_headF<<<MM2/8, 256, 0, sd>>>(aF, 512, Wx2, bx2, out2, outF, MM2);
}